// round 2
// baseline (speedup 1.0000x reference)
#include <cuda_runtime.h>
#include <cstdint>
#include <cstddef>

#define B   32
#define T   2048
#define E   512
#define H   512
#define G4  2048
#define NCTA 128
#define RTHREADS 256
#define HS_STRIDE  516   // floats per row (512 + 4 pad), 16B-aligned rows
#define HS_STRIDE4 129   // float4 units per row

// ---- device scratch (no allocations allowed in kernel_launch) ----
__device__ float g_xg[(size_t)B * T * G4];   // 512 MB: precomputed x@Wx + bx + bh
__device__ float g_hbuf[2][B * H];           // double-buffered h state
__device__ unsigned g_bar_arrive = 0;
__device__ volatile unsigned g_bar_gen = 0;

// =====================================================================
// Kernel 1: xg[m][n] = sum_k X[m][k]*Wx[k][n] + bx[n] + bh[n]
// M = B*T = 65536, N = 2048, K = 512.  128x128 tile, 8x8 per thread.
// =====================================================================
__global__ __launch_bounds__(256) void xg_gemm_kernel(
    const float* __restrict__ X, const float* __restrict__ Wx,
    const float* __restrict__ bx, const float* __restrict__ bh)
{
    __shared__ float As[8][128];   // As[k][m]
    __shared__ float Bs[8][132];   // Bs[k][n] (+pad)
    const int tid = threadIdx.x;
    const int mBase = blockIdx.y * 128;
    const int nBase = blockIdx.x * 128;
    const int arow = tid >> 1, acol = (tid & 1) * 4;   // A: 128 rows x 8 k
    const int brow = tid >> 5, bcol = (tid & 31) * 4;  // B: 8 k x 128 n
    const int tm = (tid >> 4) * 8;
    const int tn = (tid & 15) * 8;

    float acc[8][8];
    #pragma unroll
    for (int i = 0; i < 8; i++) {
        #pragma unroll
        for (int j = 0; j < 8; j++) acc[i][j] = 0.f;
    }

    const float* Aptr = X  + (size_t)(mBase + arow) * E + acol;
    const float* Bptr = Wx + (size_t)brow * G4 + nBase + bcol;

    for (int k0 = 0; k0 < E; k0 += 8) {
        float4 av = *(const float4*)(Aptr + k0);
        float4 bv = *(const float4*)(Bptr + (size_t)k0 * G4);
        __syncthreads();
        As[acol + 0][arow] = av.x;
        As[acol + 1][arow] = av.y;
        As[acol + 2][arow] = av.z;
        As[acol + 3][arow] = av.w;
        *(float4*)&Bs[brow][bcol] = bv;
        __syncthreads();
        #pragma unroll
        for (int k = 0; k < 8; k++) {
            float a[8], b[8];
            *(float4*)(a)     = *(const float4*)&As[k][tm];
            *(float4*)(a + 4) = *(const float4*)&As[k][tm + 4];
            *(float4*)(b)     = *(const float4*)&Bs[k][tn];
            *(float4*)(b + 4) = *(const float4*)&Bs[k][tn + 4];
            #pragma unroll
            for (int i = 0; i < 8; i++) {
                #pragma unroll
                for (int j = 0; j < 8; j++)
                    acc[i][j] = fmaf(a[i], b[j], acc[i][j]);
            }
        }
    }

    float bsum[8];
    #pragma unroll
    for (int j = 0; j < 8; j++)
        bsum[j] = bx[nBase + tn + j] + bh[nBase + tn + j];

    #pragma unroll
    for (int i = 0; i < 8; i++) {
        size_t row = (size_t)(mBase + tm + i);
        float4 v0 = make_float4(acc[i][0] + bsum[0], acc[i][1] + bsum[1],
                                acc[i][2] + bsum[2], acc[i][3] + bsum[3]);
        float4 v1 = make_float4(acc[i][4] + bsum[4], acc[i][5] + bsum[5],
                                acc[i][6] + bsum[6], acc[i][7] + bsum[7]);
        *(float4*)&g_xg[row * G4 + nBase + tn]     = v0;
        *(float4*)&g_xg[row * G4 + nBase + tn + 4] = v1;
    }
}

// =====================================================================
// Kernel 2: persistent LSTM recurrence.
// 128 CTAs, each owns 4 hidden units (16 gate columns).
// Per step: g[b][col] = xg[b][t][col] + sum_k h[b][k]*Wh[k][col],
// then gate activations, c/h update, grid barrier, h reload.
// col_global(c) = (c>>2)*512 + cta*4 + (c&3)   (c = gate*4 + local_hid)
// Mainloop: warp w handles k-slice [w*64, w*64+64); lane tile 4b x 4c.
// =====================================================================
__global__ __launch_bounds__(RTHREADS, 1) void lstm_rec_kernel(
    const float* __restrict__ Wh, float* __restrict__ out)
{
    extern __shared__ float sm[];
    float*  whs  = sm;                         // 16 rows x 516
    float*  hsf  = sm + 16 * HS_STRIDE;        // 32 rows x 516
    float4* red4 = (float4*)(hsf + 32 * HS_STRIDE);  // 1024 float4

    const int tid  = threadIdx.x;
    const int lane = tid & 31;
    const int w    = tid >> 5;
    const int cta  = blockIdx.x;

    // Load Wh slice: whs[c][k] = Wh[k][col_global(c)]
    for (int idx = tid; idx < 16 * 512; idx += RTHREADS) {
        int c = idx >> 9;
        int k = idx & 511;
        int col = ((c >> 2) << 9) + cta * 4 + (c & 3);
        whs[c * HS_STRIDE + k] = Wh[(size_t)k * G4 + col];
    }
    // h(0) = 0
    for (int idx = tid; idx < 32 * HS_STRIDE; idx += RTHREADS) hsf[idx] = 0.f;

    unsigned gen = g_bar_gen;   // all CTAs read before first barrier completes

    const int lb = lane & 7;    // b = lb + 8j
    const int lc = lane >> 3;   // c = lc + 4i  -> i is the gate index
    const float4* whs4 = (const float4*)whs;
    const float4* hs4c = (const float4*)hsf;
    float4*       hs4w = (float4*)hsf;

    // Reducer identity (tid < 128): owns (batch rB, hidden hid), c in register
    const int rj  = tid >> 5;                  // 0..3
    const int rB  = (lane & 7) + 8 * rj;       // batch
    const int hid = cta * 4 + (lane >> 3);     // global hidden index
    float c_state = 0.f;

    __syncthreads();

    for (int t = 0; t < T; t++) {
        // Prefetch xg for the epilogue (latency hidden under mainloop)
        float xp0 = 0.f, xp1 = 0.f, xp2 = 0.f, xp3 = 0.f;
        if (tid < 128) {
            const float* xr = g_xg + ((size_t)rB * T + t) * G4 + hid;
            xp0 = __ldcs(xr);
            xp1 = __ldcs(xr + 512);
            xp2 = __ldcs(xr + 1024);
            xp3 = __ldcs(xr + 1536);
        }

        // ---- mainloop: partial dot products over this warp's k-slice ----
        float acc[4][4];
        #pragma unroll
        for (int j = 0; j < 4; j++) {
            #pragma unroll
            for (int i = 0; i < 4; i++) acc[j][i] = 0.f;
        }
        const int kb = w * 16;  // float4 index base of this warp's 64-k slice
        #pragma unroll 4
        for (int q = 0; q < 16; q++) {
            const int kv = kb + q;
            float4 wv[4];
            #pragma unroll
            for (int i = 0; i < 4; i++)
                wv[i] = whs4[(lc + 4 * i) * HS_STRIDE4 + kv];
            #pragma unroll
            for (int j = 0; j < 4; j++) {
                float4 hh = hs4c[(lb + 8 * j) * HS_STRIDE4 + kv];
                #pragma unroll
                for (int i = 0; i < 4; i++) {
                    acc[j][i] = fmaf(hh.x, wv[i].x, acc[j][i]);
                    acc[j][i] = fmaf(hh.y, wv[i].y, acc[j][i]);
                    acc[j][i] = fmaf(hh.z, wv[i].z, acc[j][i]);
                    acc[j][i] = fmaf(hh.w, wv[i].w, acc[j][i]);
                }
            }
        }

        // ---- cross-warp (k-split) reduction: coalesced float4 layout ----
        __syncthreads();
        #pragma unroll
        for (int j = 0; j < 4; j++)
            red4[j * 256 + w * 32 + lane] =
                make_float4(acc[j][0], acc[j][1], acc[j][2], acc[j][3]);
        __syncthreads();

        // ---- epilogue: reducer holds the 4 gates of (rB, hid) ----
        if (tid < 128) {
            float4 s = make_float4(0.f, 0.f, 0.f, 0.f);
            #pragma unroll
            for (int ww = 0; ww < 8; ww++) {
                float4 v = red4[rj * 256 + ww * 32 + lane];
                s.x += v.x; s.y += v.y; s.z += v.z; s.w += v.w;
            }
            float gf = s.x + xp0;   // forget
            float gi = s.y + xp1;   // input
            float gc = s.z + xp2;   // candidate
            float go = s.w + xp3;   // output
            float f  = 1.f / (1.f + __expf(-gf));
            float ig = 1.f / (1.f + __expf(-gi));
            float cc = tanhf(gc);
            float og = 1.f / (1.f + __expf(-go));
            c_state = f * c_state + ig * cc;
            float h_new = og * tanhf(c_state);
            g_hbuf[(t + 1) & 1][rB * H + hid] = h_new;
            if (t == T - 1) {
                out[rB * H + hid]         = h_new;   // h
                out[B * H + rB * H + hid] = c_state; // c
            }
        }

        // ---- grid-wide barrier (generation-based) ----
        __syncthreads();
        if (tid == 0) {
            __threadfence();
            if (atomicAdd(&g_bar_arrive, 1u) == NCTA - 1) {
                g_bar_arrive = 0;
                __threadfence();
                g_bar_gen = gen + 1;
            } else {
                while (g_bar_gen == gen) { }
                __threadfence();
            }
        }
        __syncthreads();
        gen++;

        // ---- reload full h into SMEM for next step (L2, bypass L1) ----
        if (t < T - 1) {
            const float4* src = (const float4*)g_hbuf[(t + 1) & 1];
            #pragma unroll
            for (int q = 0; q < 16; q++) {
                int v  = tid + RTHREADS * q;
                int b  = v >> 7;
                int kk = v & 127;
                hs4w[b * HS_STRIDE4 + kk] = __ldcg(src + b * 128 + kk);
            }
            __syncthreads();
        }
    }
}

// =====================================================================
extern "C" void kernel_launch(void* const* d_in, const int* in_sizes, int n_in,
                              void* d_out, int out_size)
{
    const float* x  = (const float*)d_in[0];
    const float* Wx = (const float*)d_in[1];
    const float* Wh = (const float*)d_in[2];
    const float* bx = (const float*)d_in[3];
    const float* bh = (const float*)d_in[4];
    float* out = (float*)d_out;

    dim3 g1(G4 / 128, (B * T) / 128);
    xg_gemm_kernel<<<g1, 256>>>(x, Wx, bx, bh);

    const int smem_bytes =
        (16 * HS_STRIDE + 32 * HS_STRIDE + 4096) * (int)sizeof(float);
    cudaFuncSetAttribute(lstm_rec_kernel,
                         cudaFuncAttributeMaxDynamicSharedMemorySize, smem_bytes);
    lstm_rec_kernel<<<NCTA, RTHREADS, smem_bytes>>>(Wh, out);
}